// round 2
// baseline (speedup 1.0000x reference)
#include <cuda_runtime.h>
#include <cuda_bf16.h>

// Shapes (fixed by the problem)
#define BB 256      // batch
#define MM 8        // metapaths
#define LL 64       // walk length
#define EE 128      // embedding
#define HH 8        // heads
#define HD 16       // head dim
#define JQKV 384    // 3*E

// Scratch (no cudaMalloc allowed)
__device__ float g_agg0[BB * MM * EE];          // [B,M,E]  1 MB
__device__ float g_agg1[BB * MM * EE];          // [B,M,E]  1 MB
__device__ float g_qkv[BB * MM * JQKV];         // [(b*8+m), 384]  3 MB
__device__ float g_o[BB * MM * EE];             // attention output, row=(b*8+m)

// packed f32x2 FMA (ptxas never auto-fuses this)
__device__ __forceinline__ unsigned long long ffma2(unsigned long long a,
                                                    unsigned long long b,
                                                    unsigned long long c) {
    unsigned long long d;
    asm("fma.rn.f32x2 %0, %1, %2, %3;" : "=l"(d) : "l"(a), "l"(b), "l"(c));
    return d;
}
__device__ __forceinline__ unsigned long long pack2(float lo, float hi) {
    unsigned long long d;
    asm("mov.b64 %0, {%1, %2};" : "=l"(d) : "f"(lo), "f"(hi));
    return d;
}
__device__ __forceinline__ void unpack2(unsigned long long v, float& lo, float& hi) {
    asm("mov.b64 {%0, %1}, %2;" : "=f"(lo), "=f"(hi) : "l"(v));
}

// ---------------------------------------------------------------------------
// K1: gather + elementwise fuse + mean over L.   grid = B*M blocks, 128 thr.
// ---------------------------------------------------------------------------
__global__ __launch_bounds__(128) void k_gather(
    const int* __restrict__ walks,        // [B,M,L,3]
    const float* __restrict__ nt,         // [NUM_NODES, E]
    const float* __restrict__ fb,         // [E]
    const float* __restrict__ et)         // [8, E]
{
    __shared__ int   sw[LL * 3];
    __shared__ float se[8 * EE];
    const int t  = threadIdx.x;
    const int bm = blockIdx.x;

    for (int i = t; i < LL * 3; i += 128) sw[i] = walks[bm * (LL * 3) + i];
    for (int i = t; i < 8 * EE; i += 128) se[i] = et[i];
    const float fbv = fb[t];
    __syncthreads();

    float acc = 0.0f;
#pragma unroll 8
    for (int l = 0; l < LL; ++l) {
        const int n1 = sw[3 * l + 0];
        const int n2 = sw[3 * l + 1];
        const int ee = sw[3 * l + 2];
        const float a = nt[n1 * EE + t] + fbv;
        const float b = nt[n2 * EE + t] + fbv;
        acc += a * b * se[ee * EE + t];
    }
    g_agg0[bm * EE + t] = acc * (1.0f / (float)LL);
}

// ---------------------------------------------------------------------------
// K2: per-metapath linear.  grid = (B/8, M), 128 thr.
// ---------------------------------------------------------------------------
__global__ __launch_bounds__(128) void k_mp(
    const int* __restrict__ mpidx,
    const float* __restrict__ W,          // [M,E,E]
    const float* __restrict__ bmp)        // [M,E]
{
    __shared__ float As[8 * EE];
    const int t  = threadIdx.x;
    const int b0 = blockIdx.x * 8;
    const int m  = blockIdx.y;
    const int wm = mpidx[m];

    for (int i = t; i < 8 * EE; i += 128) {
        const int r = i >> 7, e = i & 127;
        As[i] = g_agg0[((b0 + r) * MM + m) * EE + e];
    }
    __syncthreads();

    float acc[8];
#pragma unroll
    for (int r = 0; r < 8; ++r) acc[r] = 0.0f;

    const float* Wm = W + wm * EE * EE;
    for (int e = 0; e < EE; ++e) {
        const float w = Wm[e * EE + t];
#pragma unroll
        for (int r = 0; r < 8; ++r) acc[r] += As[r * EE + e] * w;
    }
    const float bias = bmp[wm * EE + t];
#pragma unroll
    for (int r = 0; r < 8; ++r)
        g_agg1[((b0 + r) * MM + m) * EE + t] = acc[r] + bias;
}

// ---------------------------------------------------------------------------
// K3: QKV projection GEMM. rows = 2048 (b*8+m), cols = 384.
// grid = (2048/32, 3), 128 thr.
// ---------------------------------------------------------------------------
__global__ __launch_bounds__(128) void k_qkv(
    const float* __restrict__ Wq,         // [384, 128]
    const float* __restrict__ bq)         // [384]
{
    __shared__ float A_T[EE * 36];        // [e][r], stride 36
    __shared__ float Ws[128 * 33];        // [j][e-chunk], stride 33
    const int t  = threadIdx.x;
    const int r0 = blockIdx.x * 32;
    const int j0 = blockIdx.y * 128;

    for (int i = t; i < 32 * EE; i += 128) {
        const int r = i >> 7, e = i & 127;
        A_T[e * 36 + r] = g_agg1[(r0 + r) * EE + e];
    }

    unsigned long long acc2[16];
#pragma unroll
    for (int r = 0; r < 16; ++r) acc2[r] = 0ULL;

    for (int e0 = 0; e0 < EE; e0 += 32) {
        __syncthreads();
        for (int i = t; i < 128 * 32; i += 128) {
            const int j = i >> 5, e = i & 31;
            Ws[j * 33 + e] = Wq[(j0 + j) * EE + e0 + e];
        }
        __syncthreads();
#pragma unroll 4
        for (int e = 0; e < 32; ++e) {
            const float w = Ws[t * 33 + e];
            const unsigned long long ww = pack2(w, w);
            const ulonglong2* ap = (const ulonglong2*)&A_T[(e0 + e) * 36];
#pragma unroll
            for (int q = 0; q < 8; ++q) {
                ulonglong2 a = ap[q];
                acc2[2 * q + 0] = ffma2(a.x, ww, acc2[2 * q + 0]);
                acc2[2 * q + 1] = ffma2(a.y, ww, acc2[2 * q + 1]);
            }
        }
    }
    const float bias = bq[j0 + t];
#pragma unroll
    for (int q = 0; q < 16; ++q) {
        float lo, hi;
        unpack2(acc2[q], lo, hi);
        g_qkv[(r0 + 2 * q + 0) * JQKV + j0 + t] = lo + bias;
        g_qkv[(r0 + 2 * q + 1) * JQKV + j0 + t] = hi + bias;
    }
}

// ---------------------------------------------------------------------------
// K4a: attention core only (scores/softmax/AV).  grid = B blocks, 128 thr.
// writes g_o[(b*8+m)*128 + e]
// ---------------------------------------------------------------------------
__global__ __launch_bounds__(128) void k_attn_small(
    int dummy)
{
    __shared__ float s_qkv[MM * JQKV];    // [m][384]
    __shared__ float s_att[HH * MM * MM]; // [h][m][n]
    const int t = threadIdx.x;
    const int b = blockIdx.x;

    for (int i = t; i < MM * JQKV; i += 128)
        s_qkv[i] = g_qkv[b * (MM * JQKV) + i];
    __syncthreads();

    if (t < 64) {
        const int h = t >> 3;
        const int m = t & 7;
        float sc[MM];
#pragma unroll
        for (int n = 0; n < MM; ++n) {
            float s = 0.0f;
#pragma unroll
            for (int d = 0; d < HD; ++d)
                s += s_qkv[m * JQKV + h * HD + d] *
                     s_qkv[n * JQKV + EE + h * HD + d];
            sc[n] = s * 0.25f;            // 1/sqrt(16)
        }
        float mx = sc[0];
#pragma unroll
        for (int n = 1; n < MM; ++n) mx = fmaxf(mx, sc[n]);
        float sum = 0.0f;
#pragma unroll
        for (int n = 0; n < MM; ++n) { sc[n] = __expf(sc[n] - mx); sum += sc[n]; }
        const float inv = 1.0f / sum;
#pragma unroll
        for (int n = 0; n < MM; ++n)
            s_att[(h * MM + m) * MM + n] = sc[n] * inv;
    }
    __syncthreads();

    const int h = t >> 4;                 // e = t
#pragma unroll
    for (int m = 0; m < MM; ++m) {
        float v = 0.0f;
#pragma unroll
        for (int n = 0; n < MM; ++n)
            v += s_att[(h * MM + m) * MM + n] * s_qkv[n * JQKV + 2 * EE + t];
        g_o[(b * MM + m) * EE + t] = v;
    }
}

// ---------------------------------------------------------------------------
// K4b: output projection GEMM: out_rowmap( g_o[2048x128] @ Wo^T ) + bo
// grid = (2048/32, 1), 128 thr.  Same structure as k_qkv.
// Final layout: out[(m*BB + b)*EE + o], row r = b*8+m.
// ---------------------------------------------------------------------------
__global__ __launch_bounds__(128) void k_oproj(
    const float* __restrict__ Wo,         // [128,128]
    const float* __restrict__ bo,         // [128]
    float* __restrict__ out)              // [M,B,E]
{
    __shared__ float A_T[EE * 36];        // [e][r], stride 36
    __shared__ float Ws[128 * 33];
    const int t  = threadIdx.x;
    const int r0 = blockIdx.x * 32;

    for (int i = t; i < 32 * EE; i += 128) {
        const int r = i >> 7, e = i & 127;
        A_T[e * 36 + r] = g_o[(r0 + r) * EE + e];
    }

    unsigned long long acc2[16];
#pragma unroll
    for (int r = 0; r < 16; ++r) acc2[r] = 0ULL;

    for (int e0 = 0; e0 < EE; e0 += 32) {
        __syncthreads();
        for (int i = t; i < 128 * 32; i += 128) {
            const int j = i >> 5, e = i & 31;
            Ws[j * 33 + e] = Wo[j * EE + e0 + e];
        }
        __syncthreads();
#pragma unroll 4
        for (int e = 0; e < 32; ++e) {
            const float w = Ws[t * 33 + e];
            const unsigned long long ww = pack2(w, w);
            const ulonglong2* ap = (const ulonglong2*)&A_T[(e0 + e) * 36];
#pragma unroll
            for (int q = 0; q < 8; ++q) {
                ulonglong2 a = ap[q];
                acc2[2 * q + 0] = ffma2(a.x, ww, acc2[2 * q + 0]);
                acc2[2 * q + 1] = ffma2(a.y, ww, acc2[2 * q + 1]);
            }
        }
    }
    const float bias = bo[t];
#pragma unroll
    for (int q = 0; q < 16; ++q) {
        float lo, hi;
        unpack2(acc2[q], lo, hi);
        const int ra = r0 + 2 * q;        // row a
        const int rb = ra + 1;            // row b
        // row r = b*8 + m  ->  out[(m*BB + b)*EE + t]
        out[((ra & 7) * BB + (ra >> 3)) * EE + t] = lo + bias;
        out[((rb & 7) * BB + (rb >> 3)) * EE + t] = hi + bias;
    }
}

// ---------------------------------------------------------------------------
extern "C" void kernel_launch(void* const* d_in, const int* in_sizes, int n_in,
                              void* d_out, int out_size) {
    const int*   mp_type = (const int*)d_in[1];
    const int*   walks   = (const int*)d_in[2];
    const float* nt      = (const float*)d_in[3];
    const float* fb      = (const float*)d_in[4];
    const float* et      = (const float*)d_in[5];
    const float* W_mp    = (const float*)d_in[6];
    const float* b_mp    = (const float*)d_in[7];
    const float* Wqkv    = (const float*)d_in[8];
    const float* bqkv    = (const float*)d_in[9];
    const float* Wo      = (const float*)d_in[10];
    const float* bo      = (const float*)d_in[11];
    float* out = (float*)d_out;

    k_gather<<<BB * MM, 128>>>(walks, nt, fb, et);
    k_mp<<<dim3(BB / 8, MM), 128>>>(mp_type, W_mp, b_mp);
    k_qkv<<<dim3((BB * MM) / 32, 3), 128>>>(Wqkv, bqkv);
    k_attn_small<<<BB, 128>>>(0);
    k_oproj<<<(BB * MM) / 32, 128>>>(Wo, bo, out);
}

// round 4
// speedup vs baseline: 1.0021x; 1.0021x over previous
#include <cuda_runtime.h>
#include <cuda_bf16.h>

#define BB 256      // batch
#define MM 8        // metapaths
#define LL 64       // walk length
#define EE 128      // embedding
#define HH 8        // heads
#define HD 16       // head dim
#define JQKV 384    // 3*E

// Scratch (no cudaMalloc allowed)
__device__ float g_agg0[BB * MM * EE];          // [(b*8+m)][e]
__device__ float g_agg1[BB * MM * EE];          // [(b*8+m)][e]

// packed f32x2 FMA
__device__ __forceinline__ unsigned long long ffma2(unsigned long long a,
                                                    unsigned long long b,
                                                    unsigned long long c) {
    unsigned long long d;
    asm("fma.rn.f32x2 %0, %1, %2, %3;" : "=l"(d) : "l"(a), "l"(b), "l"(c));
    return d;
}
__device__ __forceinline__ unsigned long long pack2(float lo, float hi) {
    unsigned long long d;
    asm("mov.b64 %0, {%1, %2};" : "=l"(d) : "f"(lo), "f"(hi));
    return d;
}
__device__ __forceinline__ void unpack2(unsigned long long v, float& lo, float& hi) {
    asm("mov.b64 {%0, %1}, %2;" : "=f"(lo), "=f"(hi) : "l"(v));
}

// ---------------------------------------------------------------------------
// K1: gather + fuse + mean.  One warp per (b,m); 4 walks/block; float4 lanes.
// grid = 512, block = 128.
// ---------------------------------------------------------------------------
__global__ __launch_bounds__(128) void k_gather(
    const int* __restrict__ walks,        // [B,M,L,3]
    const float* __restrict__ nt,         // [NUM_NODES, E]
    const float* __restrict__ fb,         // [E]
    const float* __restrict__ et)         // [8, E]
{
    __shared__ int sw[4 * LL * 3];                      // 4 walks' indices
    __shared__ __align__(16) float se[8 * EE];          // edge table
    const int t    = threadIdx.x;
    const int lane = t & 31;
    const int w    = t >> 5;
    const int bm0  = blockIdx.x * 4;
    const int bm   = bm0 + w;

    for (int i = t; i < 4 * LL * 3; i += 128) sw[i] = walks[bm0 * (LL * 3) + i];
    for (int i = t; i < 8 * EE; i += 128)     se[i] = et[i];
    const float4  fb4 = ((const float4*)fb)[lane];
    const float4* nt4 = (const float4*)nt;
    const float4* se4 = (const float4*)se;
    __syncthreads();

    float4 acc = make_float4(0.f, 0.f, 0.f, 0.f);
    const int* swp = &sw[w * LL * 3];
#pragma unroll 4
    for (int l = 0; l < LL; ++l) {
        const int n1 = swp[3 * l + 0];
        const int n2 = swp[3 * l + 1];
        const int ey = swp[3 * l + 2];
        float4 a = nt4[n1 * 32 + lane];
        float4 b = nt4[n2 * 32 + lane];
        float4 e = se4[ey * 32 + lane];
        acc.x += (a.x + fb4.x) * (b.x + fb4.x) * e.x;
        acc.y += (a.y + fb4.y) * (b.y + fb4.y) * e.y;
        acc.z += (a.z + fb4.z) * (b.z + fb4.z) * e.z;
        acc.w += (a.w + fb4.w) * (b.w + fb4.w) * e.w;
    }
    const float s = 1.0f / (float)LL;
    acc.x *= s; acc.y *= s; acc.z *= s; acc.w *= s;
    ((float4*)g_agg0)[bm * 32 + lane] = acc;
}

// ---------------------------------------------------------------------------
// K2: per-metapath linear, 16 rows/block.  grid = (B/16, M), 128 thr.
// ---------------------------------------------------------------------------
__global__ __launch_bounds__(128) void k_mp(
    const int* __restrict__ mpidx,
    const float* __restrict__ W,          // [M,E,E] ('meo': W[m][e][o])
    const float* __restrict__ bmp)        // [M,E]
{
    __shared__ __align__(16) float At[EE * 20];   // [e][16 rows + pad4]
    const int t  = threadIdx.x;
    const int b0 = blockIdx.x * 16;
    const int m  = blockIdx.y;
    const int wm = mpidx[m];

    for (int i = t; i < 16 * EE; i += 128) {
        const int r = i >> 7, e = i & 127;
        At[e * 20 + r] = g_agg0[((b0 + r) * MM + m) * EE + e];
    }
    __syncthreads();

    unsigned long long acc2[8];
#pragma unroll
    for (int k = 0; k < 8; ++k) acc2[k] = 0ULL;

    const float* Wm = W + wm * EE * EE;
#pragma unroll 4
    for (int e = 0; e < EE; ++e) {
        const float w = Wm[e * EE + t];               // coalesced, L2 hit
        const unsigned long long ww = pack2(w, w);
        const ulonglong2* ap = (const ulonglong2*)&At[e * 20];
#pragma unroll
        for (int q = 0; q < 4; ++q) {
            ulonglong2 a = ap[q];                     // rows 4q..4q+3
            acc2[2 * q + 0] = ffma2(a.x, ww, acc2[2 * q + 0]);
            acc2[2 * q + 1] = ffma2(a.y, ww, acc2[2 * q + 1]);
        }
    }
    const float bias = bmp[wm * EE + t];
#pragma unroll
    for (int k = 0; k < 8; ++k) {
        float lo, hi;
        unpack2(acc2[k], lo, hi);
        g_agg1[((b0 + 2 * k + 0) * MM + m) * EE + t] = lo + bias;
        g_agg1[((b0 + 2 * k + 1) * MM + m) * EE + t] = hi + bias;
    }
}

// ---------------------------------------------------------------------------
// K3: fused QKV + attention + output projection.
// grid = BB/2 = 128 blocks, 256 threads, 2 batches per block.
// smem layout (floats, 48KB total):
//   [0, 4096)      Ws (swizzled 128x32 weight tile)  UNION  s_att (1024)
//   [4096, 6144)   s_ao: agg1 staged [g][e*8+m]      UNION  attn-out o
//   [6144, 12288)  s_qkv [g][m][384]
// ---------------------------------------------------------------------------
__global__ __launch_bounds__(256) void k_mha(
    const float* __restrict__ Wq,         // [384,128]
    const float* __restrict__ bq,         // [384]
    const float* __restrict__ Wo,         // [128,128]
    const float* __restrict__ bo,         // [128]
    float* __restrict__ out)              // [M,B,E]
{
    __shared__ __align__(16) float smem[12288];
    float* s_ws  = smem;                  // 4096 (swizzled)
    float* s_att = smem;                  // 1024 (union with s_ws)
    float* s_ao  = smem + 4096;           // 2048: agg1 then attn-out
    float* s_qkv = smem + 6144;           // 6144

    const int t  = threadIdx.x;
    const int g  = t >> 7;                // batch-local 0/1
    const int j  = t & 127;
    const int b0 = blockIdx.x * 2;

    // ---- Stage A: stage agg1 transposed: s_ao[g][e*8+m] ----
    for (int i = t; i < 2048; i += 256) {
        const int r = i >> 7;             // 0..15 = gg*8+m
        const int e = i & 127;
        const int gg = r >> 3, mm = r & 7;
        s_ao[gg * 1024 + e * 8 + mm] = g_agg1[((b0 + gg) * MM + mm) * EE + e];
    }

    // ---- Stage B: QKV.  thread computes qkv[g][m=0..7][j0+j] ----
    for (int jc = 0; jc < 3; ++jc) {
        const int j0 = jc * 128;
        unsigned long long acc2[4];
#pragma unroll
        for (int k = 0; k < 4; ++k) acc2[k] = 0ULL;

        for (int ec = 0; ec < 4; ++ec) {
            const int e0 = ec * 32;
            __syncthreads();              // protect prev Ws readers
            for (int i = t; i < 4096; i += 256) {
                const int jj = i >> 5, ee = i & 31;
                s_ws[jj * 32 + (ee ^ (jj & 31))] = Wq[(j0 + jj) * EE + e0 + ee];
            }
            __syncthreads();
#pragma unroll 8
            for (int e = 0; e < 32; ++e) {
                const float w = s_ws[j * 32 + (e ^ (j & 31))];
                const unsigned long long ww = pack2(w, w);
                const ulonglong2* ap =
                    (const ulonglong2*)&s_ao[g * 1024 + (e0 + e) * 8];
                ulonglong2 a0 = ap[0];    // m0..m3
                ulonglong2 a1 = ap[1];    // m4..m7
                acc2[0] = ffma2(a0.x, ww, acc2[0]);
                acc2[1] = ffma2(a0.y, ww, acc2[1]);
                acc2[2] = ffma2(a1.x, ww, acc2[2]);
                acc2[3] = ffma2(a1.y, ww, acc2[3]);
            }
        }
        const float bias = bq[j0 + j];
#pragma unroll
        for (int k = 0; k < 4; ++k) {
            float lo, hi;
            unpack2(acc2[k], lo, hi);
            s_qkv[g * 3072 + (2 * k + 0) * JQKV + j0 + j] = lo + bias;
            s_qkv[g * 3072 + (2 * k + 1) * JQKV + j0 + j] = hi + bias;
        }
    }
    __syncthreads();                      // qkv complete; Ws dead

    // ---- Stage C: attention.  scores+softmax (128 thr), AV (all) ----
    if (t < 128) {
        const int gg = t >> 6;
        const int hm = t & 63;
        const int h  = hm >> 3;
        const int m  = hm & 7;
        const float* qp = &s_qkv[gg * 3072 + m * JQKV + h * HD];
        float sc[MM];
#pragma unroll
        for (int n = 0; n < MM; ++n) {
            const float* kp = &s_qkv[gg * 3072 + n * JQKV + EE + h * HD];
            float s = 0.0f;
#pragma unroll
            for (int d = 0; d < HD; ++d) s += qp[d] * kp[d];
            sc[n] = s * 0.25f;            // 1/sqrt(16)
        }
        float mx = sc[0];
#pragma unroll
        for (int n = 1; n < MM; ++n) mx = fmaxf(mx, sc[n]);
        float sum = 0.0f;
#pragma unroll
        for (int n = 0; n < MM; ++n) { sc[n] = __expf(sc[n] - mx); sum += sc[n]; }
        const float inv = 1.0f / sum;
#pragma unroll
        for (int n = 0; n < MM; ++n)
            s_att[(gg * 64 + hm) * 8 + n] = sc[n] * inv;
    }
    __syncthreads();

    {   // AV: o[g][e][m], e = j
        const int h = j >> 4;
        const float* vp = &s_qkv[g * 3072 + 2 * EE + j];   // v[n][j] at n*384
        float ov[MM];
#pragma unroll
        for (int m = 0; m < MM; ++m) {
            float v = 0.0f;
            const float* ap = &s_att[(g * 64 + h * 8 + m) * 8];
#pragma unroll
            for (int n = 0; n < MM; ++n) v += ap[n] * vp[n * JQKV];
            ov[m] = v;
        }
        __syncthreads();                  // everyone done reading s_ao (B) & att
#pragma unroll
        for (int m = 0; m < MM; ++m)
            s_ao[g * 1024 + j * 8 + m] = ov[m];            // overwrite agg1
    }

    // ---- Stage D: output projection.  thread = output col j ----
    {
        unsigned long long acc2[4];
#pragma unroll
        for (int k = 0; k < 4; ++k) acc2[k] = 0ULL;

        for (int ec = 0; ec < 4; ++ec) {
            const int e0 = ec * 32;
            __syncthreads();
            for (int i = t; i < 4096; i += 256) {
                const int jj = i >> 5, ee = i & 31;
                s_ws[jj * 32 + (ee ^ (jj & 31))] = Wo[jj * EE + e0 + ee];
            }
            __syncthreads();
#pragma unroll 8
            for (int e = 0; e < 32; ++e) {
                const float w = s_ws[j * 32 + (e ^ (j & 31))];
                const unsigned long long ww = pack2(w, w);
                const ulonglong2* ap =
                    (const ulonglong2*)&s_ao[g * 1024 + (e0 + e) * 8];
                ulonglong2 a0 = ap[0];
                ulonglong2 a1 = ap[1];
                acc2[0] = ffma2(a0.x, ww, acc2[0]);
                acc2[1] = ffma2(a0.y, ww, acc2[1]);
                acc2[2] = ffma2(a1.x, ww, acc2[2]);
                acc2[3] = ffma2(a1.y, ww, acc2[3]);
            }
        }
        const float bias = bo[j];
        const int b = b0 + g;
#pragma unroll
        for (int k = 0; k < 4; ++k) {
            float lo, hi;
            unpack2(acc2[k], lo, hi);
            out[((2 * k + 0) * BB + b) * EE + j] = lo + bias;
            out[((2 * k + 1) * BB + b) * EE + j] = hi + bias;
        }
    }
}

// ---------------------------------------------------------------------------
extern "C" void kernel_launch(void* const* d_in, const int* in_sizes, int n_in,
                              void* d_out, int out_size) {
    const int*   mp_type = (const int*)d_in[1];
    const int*   walks   = (const int*)d_in[2];
    const float* nt      = (const float*)d_in[3];
    const float* fb      = (const float*)d_in[4];
    const float* et      = (const float*)d_in[5];
    const float* W_mp    = (const float*)d_in[6];
    const float* b_mp    = (const float*)d_in[7];
    const float* Wqkv    = (const float*)d_in[8];
    const float* bqkv    = (const float*)d_in[9];
    const float* Wo      = (const float*)d_in[10];
    const float* bo      = (const float*)d_in[11];
    float* out = (float*)d_out;

    k_gather<<<(BB * MM) / 4, 128>>>(walks, nt, fb, et);
    k_mp<<<dim3(BB / 16, MM), 128>>>(mp_type, W_mp, b_mp);
    k_mha<<<BB / 2, 256>>>(Wqkv, bqkv, Wo, bo, out);
}

// round 9
// speedup vs baseline: 1.3003x; 1.2975x over previous
#include <cuda_runtime.h>
#include <cuda_bf16.h>

#define BB 256      // batch
#define MM 8        // metapaths
#define LL 64       // walk length
#define EE 128      // embedding
#define HH 8        // heads
#define HD 16       // head dim
#define JQKV 384    // 3*E

// Scratch (no cudaMalloc allowed)
__device__ float g_agg0[BB * MM * EE];          // [(b*8+m)][e]
__device__ float g_agg1[BB * MM * EE];          // [(b*8+m)][e]

// packed f32x2 FMA
__device__ __forceinline__ unsigned long long ffma2(unsigned long long a,
                                                    unsigned long long b,
                                                    unsigned long long c) {
    unsigned long long d;
    asm("fma.rn.f32x2 %0, %1, %2, %3;" : "=l"(d) : "l"(a), "l"(b), "l"(c));
    return d;
}
__device__ __forceinline__ unsigned long long pack2(float lo, float hi) {
    unsigned long long d;
    asm("mov.b64 %0, {%1, %2};" : "=l"(d) : "f"(lo), "f"(hi));
    return d;
}
__device__ __forceinline__ void unpack2(unsigned long long v, float& lo, float& hi) {
    asm("mov.b64 {%0, %1}, %2;" : "=f"(lo), "=f"(hi) : "l"(v));
}

// ---------------------------------------------------------------------------
// K1: gather + fuse + mean, L-SPLIT for occupancy.
// Block = 256 thr (8 warps) = 2 walks x 4 warp-segments x 16 steps.
// grid = 2048/2 = 1024 blocks  ->  8192 warps  ->  ~87% occupancy.
// ---------------------------------------------------------------------------
__global__ __launch_bounds__(256) void k_gather(
    const int* __restrict__ walks,        // [B,M,L,3]
    const float* __restrict__ nt,         // [NUM_NODES, E]
    const float* __restrict__ fb,         // [E]
    const float* __restrict__ et)         // [8, E]
{
    __shared__ int sw[2 * LL * 3];                      // 2 walks' indices
    __shared__ __align__(16) float se[8 * EE];          // edge table
    __shared__ __align__(16) float s_red[8 * EE];       // 8 warp partials
    const int t    = threadIdx.x;
    const int lane = t & 31;
    const int w    = t >> 5;
    const int wk   = w >> 2;              // walk within block (0/1)
    const int seg  = w & 3;               // L-segment (0..3)
    const int bm0  = blockIdx.x * 2;

    for (int i = t; i < 2 * LL * 3; i += 256) sw[i] = walks[bm0 * (LL * 3) + i];
    for (int i = t; i < 8 * EE; i += 256)     se[i] = et[i];
    const float4  fb4 = ((const float4*)fb)[lane];
    const float4* nt4 = (const float4*)nt;
    const float4* se4 = (const float4*)se;
    __syncthreads();

    float4 acc = make_float4(0.f, 0.f, 0.f, 0.f);
    const int* swp = &sw[wk * (LL * 3) + seg * 48];     // 16 steps * 3
#pragma unroll 4
    for (int l = 0; l < 16; ++l) {
        const int n1 = swp[3 * l + 0];
        const int n2 = swp[3 * l + 1];
        const int ey = swp[3 * l + 2];
        float4 a = nt4[n1 * 32 + lane];
        float4 b = nt4[n2 * 32 + lane];
        float4 e = se4[ey * 32 + lane];
        acc.x += (a.x + fb4.x) * (b.x + fb4.x) * e.x;
        acc.y += (a.y + fb4.y) * (b.y + fb4.y) * e.y;
        acc.z += (a.z + fb4.z) * (b.z + fb4.z) * e.z;
        acc.w += (a.w + fb4.w) * (b.w + fb4.w) * e.w;
    }
    ((float4*)s_red)[w * 32 + lane] = acc;
    __syncthreads();

    // reduce 4 warp-partials per walk: thread t -> (walk = t>>7, e = t&127)
    const int wk2 = t >> 7;
    const int e   = t & 127;
    const float s = (s_red[(wk2 * 4 + 0) * EE + e] +
                     s_red[(wk2 * 4 + 1) * EE + e] +
                     s_red[(wk2 * 4 + 2) * EE + e] +
                     s_red[(wk2 * 4 + 3) * EE + e]) * (1.0f / (float)LL);
    g_agg0[(bm0 + wk2) * EE + e] = s;
}

// ---------------------------------------------------------------------------
// K2: per-metapath linear, 8 rows/block.  grid = (B/8, M) = 256 blocks.
// ---------------------------------------------------------------------------
__global__ __launch_bounds__(128) void k_mp(
    const int* __restrict__ mpidx,
    const float* __restrict__ W,          // [M,E,E] ('meo': W[m][e][o])
    const float* __restrict__ bmp)        // [M,E]
{
    __shared__ __align__(16) float At[EE * 8];    // [e][8 rows]
    const int t  = threadIdx.x;
    const int b0 = blockIdx.x * 8;
    const int m  = blockIdx.y;
    const int wm = mpidx[m];

    for (int i = t; i < 8 * EE; i += 128) {
        const int r = i >> 7, e = i & 127;
        At[e * 8 + r] = g_agg0[((b0 + r) * MM + m) * EE + e];
    }
    __syncthreads();

    unsigned long long acc2[4];
#pragma unroll
    for (int k = 0; k < 4; ++k) acc2[k] = 0ULL;

    const float* Wm = W + wm * EE * EE;
#pragma unroll 8
    for (int e = 0; e < EE; ++e) {
        const float w = Wm[e * EE + t];               // coalesced, L2 hit
        const unsigned long long ww = pack2(w, w);
        const ulonglong2* ap = (const ulonglong2*)&At[e * 8];
        ulonglong2 a0 = ap[0];                        // rows 0..3 (broadcast)
        ulonglong2 a1 = ap[1];                        // rows 4..7
        acc2[0] = ffma2(a0.x, ww, acc2[0]);
        acc2[1] = ffma2(a0.y, ww, acc2[1]);
        acc2[2] = ffma2(a1.x, ww, acc2[2]);
        acc2[3] = ffma2(a1.y, ww, acc2[3]);
    }
    const float bias = bmp[wm * EE + t];
#pragma unroll
    for (int k = 0; k < 4; ++k) {
        float lo, hi;
        unpack2(acc2[k], lo, hi);
        g_agg1[((b0 + 2 * k + 0) * MM + m) * EE + t] = lo + bias;
        g_agg1[((b0 + 2 * k + 1) * MM + m) * EE + t] = hi + bias;
    }
}

// ---------------------------------------------------------------------------
// K3: fused QKV + attention + output projection.
// grid = BB/2 = 128 blocks, 256 threads, 2 batches per block.
// ---------------------------------------------------------------------------
__global__ __launch_bounds__(256) void k_mha(
    const float* __restrict__ Wq,         // [384,128]
    const float* __restrict__ bq,         // [384]
    const float* __restrict__ Wo,         // [128,128]
    const float* __restrict__ bo,         // [128]
    float* __restrict__ out)              // [M,B,E]
{
    __shared__ __align__(16) float smem[12288];
    float* s_ws  = smem;                  // 4096 (swizzled weight chunk)
    float* s_att = smem;                  // 1024 (union with s_ws)
    float* s_ao  = smem + 4096;           // 2048: agg1 then attn-out
    float* s_qkv = smem + 6144;           // 6144

    const int t  = threadIdx.x;
    const int g  = t >> 7;                // batch-local 0/1
    const int j  = t & 127;
    const int b0 = blockIdx.x * 2;

    // ---- Stage A: stage agg1 transposed: s_ao[g][e*8+m] ----
    for (int i = t; i < 2048; i += 256) {
        const int r = i >> 7;             // 0..15 = gg*8+m
        const int e = i & 127;
        const int gg = r >> 3, mm = r & 7;
        s_ao[gg * 1024 + e * 8 + mm] = g_agg1[((b0 + gg) * MM + mm) * EE + e];
    }

    // ---- Stage B: QKV ----
    for (int jc = 0; jc < 3; ++jc) {
        const int j0 = jc * 128;
        unsigned long long acc2[4];
#pragma unroll
        for (int k = 0; k < 4; ++k) acc2[k] = 0ULL;

        for (int ec = 0; ec < 4; ++ec) {
            const int e0 = ec * 32;
            __syncthreads();
            for (int i = t; i < 4096; i += 256) {
                const int jj = i >> 5, ee = i & 31;
                s_ws[jj * 32 + (ee ^ (jj & 31))] = Wq[(j0 + jj) * EE + e0 + ee];
            }
            __syncthreads();
#pragma unroll 8
            for (int e = 0; e < 32; ++e) {
                const float w = s_ws[j * 32 + (e ^ (j & 31))];
                const unsigned long long ww = pack2(w, w);
                const ulonglong2* ap =
                    (const ulonglong2*)&s_ao[g * 1024 + (e0 + e) * 8];
                ulonglong2 a0 = ap[0];
                ulonglong2 a1 = ap[1];
                acc2[0] = ffma2(a0.x, ww, acc2[0]);
                acc2[1] = ffma2(a0.y, ww, acc2[1]);
                acc2[2] = ffma2(a1.x, ww, acc2[2]);
                acc2[3] = ffma2(a1.y, ww, acc2[3]);
            }
        }
        const float bias = bq[j0 + j];
#pragma unroll
        for (int k = 0; k < 4; ++k) {
            float lo, hi;
            unpack2(acc2[k], lo, hi);
            s_qkv[g * 3072 + (2 * k + 0) * JQKV + j0 + j] = lo + bias;
            s_qkv[g * 3072 + (2 * k + 1) * JQKV + j0 + j] = hi + bias;
        }
    }
    __syncthreads();

    // ---- Stage C: attention ----
    if (t < 128) {
        const int gg = t >> 6;
        const int hm = t & 63;
        const int h  = hm >> 3;
        const int m  = hm & 7;
        const float* qp = &s_qkv[gg * 3072 + m * JQKV + h * HD];
        float sc[MM];
#pragma unroll
        for (int n = 0; n < MM; ++n) {
            const float* kp = &s_qkv[gg * 3072 + n * JQKV + EE + h * HD];
            float s = 0.0f;
#pragma unroll
            for (int d = 0; d < HD; ++d) s += qp[d] * kp[d];
            sc[n] = s * 0.25f;            // 1/sqrt(16)
        }
        float mx = sc[0];
#pragma unroll
        for (int n = 1; n < MM; ++n) mx = fmaxf(mx, sc[n]);
        float sum = 0.0f;
#pragma unroll
        for (int n = 0; n < MM; ++n) { sc[n] = __expf(sc[n] - mx); sum += sc[n]; }
        const float inv = 1.0f / sum;
#pragma unroll
        for (int n = 0; n < MM; ++n)
            s_att[(gg * 64 + hm) * 8 + n] = sc[n] * inv;
    }
    __syncthreads();

    {   // AV: o[g][e][m], e = j
        const int h = j >> 4;
        const float* vp = &s_qkv[g * 3072 + 2 * EE + j];
        float ov[MM];
#pragma unroll
        for (int m = 0; m < MM; ++m) {
            float v = 0.0f;
            const float* ap = &s_att[(g * 64 + h * 8 + m) * 8];
#pragma unroll
            for (int n = 0; n < MM; ++n) v += ap[n] * vp[n * JQKV];
            ov[m] = v;
        }
        __syncthreads();
#pragma unroll
        for (int m = 0; m < MM; ++m)
            s_ao[g * 1024 + j * 8 + m] = ov[m];
    }

    // ---- Stage D: output projection ----
    {
        unsigned long long acc2[4];
#pragma unroll
        for (int k = 0; k < 4; ++k) acc2[k] = 0ULL;

        for (int ec = 0; ec < 4; ++ec) {
            const int e0 = ec * 32;
            __syncthreads();
            for (int i = t; i < 4096; i += 256) {
                const int jj = i >> 5, ee = i & 31;
                s_ws[jj * 32 + (ee ^ (jj & 31))] = Wo[jj * EE + e0 + ee];
            }
            __syncthreads();
#pragma unroll 8
            for (int e = 0; e < 32; ++e) {
                const float w = s_ws[j * 32 + (e ^ (j & 31))];
                const unsigned long long ww = pack2(w, w);
                const ulonglong2* ap =
                    (const ulonglong2*)&s_ao[g * 1024 + (e0 + e) * 8];
                ulonglong2 a0 = ap[0];
                ulonglong2 a1 = ap[1];
                acc2[0] = ffma2(a0.x, ww, acc2[0]);
                acc2[1] = ffma2(a0.y, ww, acc2[1]);
                acc2[2] = ffma2(a1.x, ww, acc2[2]);
                acc2[3] = ffma2(a1.y, ww, acc2[3]);
            }
        }
        const float bias = bo[j];
        const int b = b0 + g;
#pragma unroll
        for (int k = 0; k < 4; ++k) {
            float lo, hi;
            unpack2(acc2[k], lo, hi);
            out[((2 * k + 0) * BB + b) * EE + j] = lo + bias;
            out[((2 * k + 1) * BB + b) * EE + j] = hi + bias;
        }
    }
}

// ---------------------------------------------------------------------------
extern "C" void kernel_launch(void* const* d_in, const int* in_sizes, int n_in,
                              void* d_out, int out_size) {
    const int*   mp_type = (const int*)d_in[1];
    const int*   walks   = (const int*)d_in[2];
    const float* nt      = (const float*)d_in[3];
    const float* fb      = (const float*)d_in[4];
    const float* et      = (const float*)d_in[5];
    const float* W_mp    = (const float*)d_in[6];
    const float* b_mp    = (const float*)d_in[7];
    const float* Wqkv    = (const float*)d_in[8];
    const float* bqkv    = (const float*)d_in[9];
    const float* Wo      = (const float*)d_in[10];
    const float* bo      = (const float*)d_in[11];
    float* out = (float*)d_out;

    k_gather<<<(BB * MM) / 2, 256>>>(walks, nt, fb, et);
    k_mp<<<dim3(BB / 8, MM), 128>>>(mp_type, W_mp, b_mp);
    k_mha<<<BB / 2, 256>>>(Wqkv, bqkv, Wo, bo, out);
}

// round 10
// speedup vs baseline: 1.4636x; 1.1256x over previous
#include <cuda_runtime.h>
#include <cuda_bf16.h>

#define BB 256      // batch
#define MM 8        // metapaths
#define LL 64       // walk length
#define EE 128      // embedding
#define HH 8        // heads
#define HD 16       // head dim
#define JQKV 384    // 3*E

// Scratch (no cudaMalloc allowed)
__device__ float g_agg0[BB * MM * EE];          // [(b*8+m)][e]
__device__ float g_agg1[BB * MM * EE];          // [(b*8+m)][e]

// packed f32x2 FMA
__device__ __forceinline__ unsigned long long ffma2(unsigned long long a,
                                                    unsigned long long b,
                                                    unsigned long long c) {
    unsigned long long d;
    asm("fma.rn.f32x2 %0, %1, %2, %3;" : "=l"(d) : "l"(a), "l"(b), "l"(c));
    return d;
}
__device__ __forceinline__ unsigned long long pack2(float lo, float hi) {
    unsigned long long d;
    asm("mov.b64 %0, {%1, %2};" : "=l"(d) : "f"(lo), "f"(hi));
    return d;
}
__device__ __forceinline__ void unpack2(unsigned long long v, float& lo, float& hi) {
    asm("mov.b64 {%0, %1}, %2;" : "=f"(lo), "=f"(hi) : "l"(v));
}

// ---------------------------------------------------------------------------
// K1: gather + fuse + mean.  1 walk per block, 128 thr = 4 warps x 16 steps.
// grid = 2048 blocks -> ~14 blocks/SM -> ~85%+ occupancy.
// ---------------------------------------------------------------------------
__global__ __launch_bounds__(128) void k_gather(
    const int* __restrict__ walks,        // [B,M,L,3]
    const float* __restrict__ nt,         // [NUM_NODES, E]
    const float* __restrict__ fb,         // [E]
    const float* __restrict__ et)         // [8, E]
{
    __shared__ int sw[LL * 3];
    __shared__ __align__(16) float se[8 * EE];
    __shared__ __align__(16) float s_red[4 * EE];
    const int t    = threadIdx.x;
    const int lane = t & 31;
    const int w    = t >> 5;              // warp = L-segment 0..3
    const int bm   = blockIdx.x;

    for (int i = t; i < LL * 3; i += 128) sw[i] = walks[bm * (LL * 3) + i];
    for (int i = t; i < 8 * EE; i += 128) se[i] = et[i];
    const float4  fb4 = ((const float4*)fb)[lane];
    const float4* nt4 = (const float4*)nt;
    const float4* se4 = (const float4*)se;
    __syncthreads();

    float4 acc = make_float4(0.f, 0.f, 0.f, 0.f);
    const int* swp = &sw[w * 48];         // 16 steps * 3
#pragma unroll 4
    for (int l = 0; l < 16; ++l) {
        const int n1 = swp[3 * l + 0];
        const int n2 = swp[3 * l + 1];
        const int ey = swp[3 * l + 2];
        float4 a = nt4[n1 * 32 + lane];
        float4 b = nt4[n2 * 32 + lane];
        float4 e = se4[ey * 32 + lane];
        acc.x += (a.x + fb4.x) * (b.x + fb4.x) * e.x;
        acc.y += (a.y + fb4.y) * (b.y + fb4.y) * e.y;
        acc.z += (a.z + fb4.z) * (b.z + fb4.z) * e.z;
        acc.w += (a.w + fb4.w) * (b.w + fb4.w) * e.w;
    }
    ((float4*)s_red)[w * 32 + lane] = acc;
    __syncthreads();

    const float s = (s_red[0 * EE + t] + s_red[1 * EE + t] +
                     s_red[2 * EE + t] + s_red[3 * EE + t]) * (1.0f / (float)LL);
    g_agg0[bm * EE + t] = s;
}

// ---------------------------------------------------------------------------
// K2: per-metapath linear, 8 rows/block, e-dim split over 2 thread halves.
// grid = (B/8, M) = 256 blocks, 256 thr.
// ---------------------------------------------------------------------------
__global__ __launch_bounds__(256) void k_mp(
    const int* __restrict__ mpidx,
    const float* __restrict__ W,          // [M,E,E] ('meo': W[m][e][o])
    const float* __restrict__ bmp)        // [M,E]
{
    __shared__ __align__(16) float At[EE * 8];    // [e][r]
    __shared__ __align__(16) float s_red[2 * 1024]; // [h][o*8+r]
    const int t  = threadIdx.x;
    const int o  = t & 127;
    const int h  = t >> 7;                // e-half
    const int b0 = blockIdx.x * 8;
    const int m  = blockIdx.y;
    const int wm = mpidx[m];

    for (int i = t; i < 8 * EE; i += 256) {
        const int r = i >> 7, e = i & 127;
        At[e * 8 + r] = g_agg0[((b0 + r) * MM + m) * EE + e];
    }
    __syncthreads();

    unsigned long long acc2[4];
#pragma unroll
    for (int k = 0; k < 4; ++k) acc2[k] = 0ULL;

    const float* Wm = W + wm * EE * EE + (h * 64) * EE;
    const float* Ab = &At[(h * 64) * 8];
#pragma unroll 8
    for (int e = 0; e < 64; ++e) {
        const float w = Wm[e * EE + o];
        const unsigned long long ww = pack2(w, w);
        const ulonglong2* ap = (const ulonglong2*)&Ab[e * 8];
        ulonglong2 a0 = ap[0];
        ulonglong2 a1 = ap[1];
        acc2[0] = ffma2(a0.x, ww, acc2[0]);
        acc2[1] = ffma2(a0.y, ww, acc2[1]);
        acc2[2] = ffma2(a1.x, ww, acc2[2]);
        acc2[3] = ffma2(a1.y, ww, acc2[3]);
    }
#pragma unroll
    for (int k = 0; k < 4; ++k) {
        float lo, hi;
        unpack2(acc2[k], lo, hi);
        s_red[h * 1024 + o * 8 + 2 * k + 0] = lo;
        s_red[h * 1024 + o * 8 + 2 * k + 1] = hi;
    }
    __syncthreads();

    const float bias = bmp[wm * EE + o];
#pragma unroll
    for (int k = 0; k < 4; ++k) {
        const int r = k * 2 + h;          // rows 0..7, coalesced in o
        const float v = s_red[0 * 1024 + o * 8 + r] +
                        s_red[1 * 1024 + o * 8 + r] + bias;
        g_agg1[((b0 + r) * MM + m) * EE + o] = v;
    }
}

// ---------------------------------------------------------------------------
// K3: fused QKV + attention + output projection.
// grid = 128 blocks, 256 thr, 2 batches/block.  Dynamic smem = 96 KB:
//   s_ws  [16384) full 128x128 weight chunk (swizzled)  UNION s_att (1024)
//   s_ao  [16384,18432)  agg1 staged / attn-out, [g][e*8+m]
//   s_qkv [18432,24576)  [g][m][384]
// Only 4 weight stage/barrier pairs total (3 QKV chunks + Wo).
// ---------------------------------------------------------------------------
__global__ __launch_bounds__(256) void k_mha(
    const float* __restrict__ Wq,         // [384,128]
    const float* __restrict__ bq,         // [384]
    const float* __restrict__ Wo,         // [128,128]
    const float* __restrict__ bo,         // [128]
    float* __restrict__ out)              // [M,B,E]
{
    extern __shared__ __align__(16) float smem[];
    float* s_ws  = smem;                  // 16384
    float* s_att = smem;                  // 1024 (union with s_ws)
    float* s_ao  = smem + 16384;          // 2048
    float* s_qkv = smem + 18432;          // 6144

    const int t  = threadIdx.x;
    const int g  = t >> 7;                // batch-local 0/1
    const int j  = t & 127;
    const int b0 = blockIdx.x * 2;

    // ---- Stage A: stage agg1 transposed: s_ao[g][e*8+m] ----
    for (int i = t; i < 2048; i += 256) {
        const int r = i >> 7;             // gg*8+m
        const int e = i & 127;
        const int gg = r >> 3, mm = r & 7;
        s_ao[gg * 1024 + e * 8 + mm] = g_agg1[((b0 + gg) * MM + mm) * EE + e];
    }

    // ---- Stage B: QKV, one full 128x128 weight chunk per jc ----
    for (int jc = 0; jc < 3; ++jc) {
        const int j0 = jc * 128;
        __syncthreads();                  // protect prev s_ws readers / s_ao
        for (int i = t; i < 16384; i += 256) {
            const int jj = i >> 7, ee = i & 127;
            s_ws[jj * 128 + (ee ^ (jj & 31))] = Wq[(j0 + jj) * EE + ee];
        }
        __syncthreads();

        unsigned long long acc2[4];
#pragma unroll
        for (int k = 0; k < 4; ++k) acc2[k] = 0ULL;
#pragma unroll 8
        for (int e = 0; e < 128; ++e) {
            const float w = s_ws[j * 128 + (e ^ (j & 31))];
            const unsigned long long ww = pack2(w, w);
            const ulonglong2* ap = (const ulonglong2*)&s_ao[g * 1024 + e * 8];
            ulonglong2 a0 = ap[0];
            ulonglong2 a1 = ap[1];
            acc2[0] = ffma2(a0.x, ww, acc2[0]);
            acc2[1] = ffma2(a0.y, ww, acc2[1]);
            acc2[2] = ffma2(a1.x, ww, acc2[2]);
            acc2[3] = ffma2(a1.y, ww, acc2[3]);
        }
        const float bias = bq[j0 + j];
#pragma unroll
        for (int k = 0; k < 4; ++k) {
            float lo, hi;
            unpack2(acc2[k], lo, hi);
            s_qkv[g * 3072 + (2 * k + 0) * JQKV + j0 + j] = lo + bias;
            s_qkv[g * 3072 + (2 * k + 1) * JQKV + j0 + j] = hi + bias;
        }
    }
    __syncthreads();                      // qkv complete; s_ws dead

    // ---- Stage C: attention ----
    if (t < 128) {
        const int gg = t >> 6;
        const int hm = t & 63;
        const int h  = hm >> 3;
        const int m  = hm & 7;
        const float* qp = &s_qkv[gg * 3072 + m * JQKV + h * HD];
        float sc[MM];
#pragma unroll
        for (int n = 0; n < MM; ++n) {
            const float* kp = &s_qkv[gg * 3072 + n * JQKV + EE + h * HD];
            float s = 0.0f;
#pragma unroll
            for (int d = 0; d < HD; ++d) s += qp[d] * kp[d];
            sc[n] = s * 0.25f;            // 1/sqrt(16)
        }
        float mx = sc[0];
#pragma unroll
        for (int n = 1; n < MM; ++n) mx = fmaxf(mx, sc[n]);
        float sum = 0.0f;
#pragma unroll
        for (int n = 0; n < MM; ++n) { sc[n] = __expf(sc[n] - mx); sum += sc[n]; }
        const float inv = 1.0f / sum;
#pragma unroll
        for (int n = 0; n < MM; ++n)
            s_att[(gg * 64 + hm) * 8 + n] = sc[n] * inv;
    }
    __syncthreads();

    {   // AV: o[g][e][m], e = j
        const int h = j >> 4;
        const float* vp = &s_qkv[g * 3072 + 2 * EE + j];
        float ov[MM];
#pragma unroll
        for (int m = 0; m < MM; ++m) {
            float v = 0.0f;
            const float* ap = &s_att[(g * 64 + h * 8 + m) * 8];
#pragma unroll
            for (int n = 0; n < MM; ++n) v += ap[n] * vp[n * JQKV];
            ov[m] = v;
        }
        __syncthreads();                  // done reading s_ao & s_att
#pragma unroll
        for (int m = 0; m < MM; ++m)
            s_ao[g * 1024 + j * 8 + m] = ov[m];
    }
    __syncthreads();                      // s_ao attn-out ready; s_att dead

    // ---- Stage D: output projection, single weight stage ----
    {
        for (int i = t; i < 16384; i += 256) {
            const int jj = i >> 7, ee = i & 127;
            s_ws[jj * 128 + (ee ^ (jj & 31))] = Wo[jj * EE + ee];
        }
        __syncthreads();

        unsigned long long acc2[4];
#pragma unroll
        for (int k = 0; k < 4; ++k) acc2[k] = 0ULL;
#pragma unroll 8
        for (int e = 0; e < 128; ++e) {
            const float w = s_ws[j * 128 + (e ^ (j & 31))];
            const unsigned long long ww = pack2(w, w);
            const ulonglong2* ap = (const ulonglong2*)&s_ao[g * 1024 + e * 8];
            ulonglong2 a0 = ap[0];
            ulonglong2 a1 = ap[1];
            acc2[0] = ffma2(a0.x, ww, acc2[0]);
            acc2[1] = ffma2(a0.y, ww, acc2[1]);
            acc2[2] = ffma2(a1.x, ww, acc2[2]);
            acc2[3] = ffma2(a1.y, ww, acc2[3]);
        }
        const float bias = bo[j];
        const int b = b0 + g;
#pragma unroll
        for (int k = 0; k < 4; ++k) {
            float lo, hi;
            unpack2(acc2[k], lo, hi);
            out[((2 * k + 0) * BB + b) * EE + j] = lo + bias;
            out[((2 * k + 1) * BB + b) * EE + j] = hi + bias;
        }
    }
}

// ---------------------------------------------------------------------------
extern "C" void kernel_launch(void* const* d_in, const int* in_sizes, int n_in,
                              void* d_out, int out_size) {
    const int*   mp_type = (const int*)d_in[1];
    const int*   walks   = (const int*)d_in[2];
    const float* nt      = (const float*)d_in[3];
    const float* fb      = (const float*)d_in[4];
    const float* et      = (const float*)d_in[5];
    const float* W_mp    = (const float*)d_in[6];
    const float* b_mp    = (const float*)d_in[7];
    const float* Wqkv    = (const float*)d_in[8];
    const float* bqkv    = (const float*)d_in[9];
    const float* Wo      = (const float*)d_in[10];
    const float* bo      = (const float*)d_in[11];
    float* out = (float*)d_out;

    static const size_t MHA_SMEM = 24576 * sizeof(float);   // 96 KB
    cudaFuncSetAttribute(k_mha, cudaFuncAttributeMaxDynamicSharedMemorySize,
                         (int)MHA_SMEM);

    k_gather<<<BB * MM, 128>>>(walks, nt, fb, et);
    k_mp<<<dim3(BB / 8, MM), 256>>>(mp_type, W_mp, b_mp);
    k_mha<<<BB / 2, 256, MHA_SMEM>>>(Wqkv, bqkv, Wo, bo, out);
}